// round 11
// baseline (speedup 1.0000x reference)
#include <cuda_runtime.h>

#define SQH 0.70710678118654752440f

__constant__ float c_h0o[5], c_h1o[7], c_h0a[10], c_h0b[10], c_h1a[10], c_h1b[10];

// scratch lowpass pyramids (64 planes)
__device__ float g_ll1[64u * 512u * 512u];  // 64 MB
__device__ float g_ll2[64u * 256u * 256u];  // 16 MB

__device__ __forceinline__ int refl(int p, int r) {
    if (p < 0) p = -1 - p;
    if (p >= r) p = 2 * r - 1 - p;
    return p;
}

// packed fp32x2 FMA (Blackwell): d = a*b + c per lane
__device__ __forceinline__ float2 ffma2(float2 a, float2 b, float2 c) {
    float2 d;
    asm("fma.rn.f32x2 %0, %1, %2, %3;"
        : "=l"(reinterpret_cast<unsigned long long&>(d))
        : "l"(reinterpret_cast<unsigned long long&>(a)),
          "l"(reinterpret_cast<unsigned long long&>(b)),
          "l"(reinterpret_cast<unsigned long long&>(c)));
    return d;
}
__device__ __forceinline__ float2 dup2(float v) { return make_float2(v, v); }

// ---------------------------------------------------------------------------
// Level 1: tile 64(h) x 64(w), 512 threads, 3 blocks/SM (48 warps).
// Dynamic smem: sx 70x76 | slo 70x68 | shi 70x68  = 59360 B.
// (unchanged from R10: measured 75.8us, occ 68.9%)
// ---------------------------------------------------------------------------
constexpr int SX1 = 76;
constexpr int SL1 = 68;
constexpr int L1_SMEM = (70 * SX1 + 2 * 70 * SL1) * 4;

__global__ __launch_bounds__(512, 3) void k_level1(const float* __restrict__ x,
                                                   float* __restrict__ yh0) {
    extern __shared__ float smem[];
    float* sx = smem;                  // 70 * 76
    float* slo = smem + 70 * SX1;      // 70 * 68
    float* shi = slo + 70 * SL1;       // 70 * 68
    const int plane = blockIdx.z;
    const int tx0 = blockIdx.x * 64, ty0 = blockIdx.y * 64;
    const int tid = threadIdx.x;
    const float* xp = x + (size_t)plane * 262144;

    // ---- load x tile: rows ty0-3..+66, cols tx0-3..+66 (70x70) ----
    if (ty0 >= 3 && ty0 + 67 <= 512 && tx0 >= 3 && tx0 + 67 <= 512) {
        const float* p0 = xp + (ty0 - 3) * 512 + (tx0 - 3);
#pragma unroll
        for (int k = 0; k < 10; ++k) {
            int idx = tid + k * 512;
            if (idx < 4900) {
                int rr = idx / 70, cc = idx - rr * 70;
                sx[rr * SX1 + cc] = p0[rr * 512 + cc];
            }
        }
    } else {
        for (int idx = tid; idx < 4900; idx += 512) {
            int rr = idx / 70, cc = idx - rr * 70;
            sx[rr * SX1 + cc] = xp[(size_t)refl(ty0 - 3 + rr, 512) * 512 + refl(tx0 - 3 + cc, 512)];
        }
    }
    __syncthreads();

    // ---- row filter: 70 rows x 8 chunks of 8 cols = 560 units ----
    for (int idx = tid; idx < 560; idx += 512) {
        int r = idx % 70, chunk = idx / 70;
        const float* rp = &sx[r * SX1 + chunk * 8];
        float xr[16];
        ((float4*)xr)[0] = *(const float4*)rp;
        ((float4*)xr)[1] = *(const float4*)(rp + 4);
        ((float4*)xr)[2] = *(const float4*)(rp + 8);
        ((float4*)xr)[3] = *(const float4*)(rp + 12);
        float* sl = &slo[r * SL1 + chunk * 8];
        float* sh = &shi[r * SL1 + chunk * 8];
#pragma unroll
        for (int g = 0; g < 2; ++g) {
            float v0 = 0.f, v1 = 0.f, v2 = 0.f, v3 = 0.f;
#pragma unroll
            for (int j = 0; j < 5; ++j) {
                float h = c_h0o[4 - j];
                v0 = fmaf(h, xr[4 * g + 1 + j], v0);
                v1 = fmaf(h, xr[4 * g + 2 + j], v1);
                v2 = fmaf(h, xr[4 * g + 3 + j], v2);
                v3 = fmaf(h, xr[4 * g + 4 + j], v3);
            }
            *(float4*)(sl + 4 * g) = make_float4(v0, v1, v2, v3);
        }
#pragma unroll
        for (int g = 0; g < 2; ++g) {
            float v0 = 0.f, v1 = 0.f, v2 = 0.f, v3 = 0.f;
#pragma unroll
            for (int j = 0; j < 7; ++j) {
                float h = c_h1o[6 - j];
                v0 = fmaf(h, xr[4 * g + j], v0);
                v1 = fmaf(h, xr[4 * g + 1 + j], v1);
                v2 = fmaf(h, xr[4 * g + 2 + j], v2);
                v3 = fmaf(h, xr[4 * g + 3 + j], v3);
            }
            *(float4*)(sh + 4 * g) = make_float4(v0, v1, v2, v3);
        }
    }
    __syncthreads();

    // ---- col filters + ll + q2c: 2 q-row units per thread ----
    const int qx = tid & 31;
    const int qr0 = tid >> 5;  // 0..15
    float2* yo = (float2*)yh0;
    const size_t pb = (size_t)plane * 6;
    const int gqx = (tx0 >> 1) + qx;
#pragma unroll
    for (int half = 0; half < 2; ++half) {
        const int qr = qr0 + 16 * half;
        const int rb = 2 * qr;
        float2 lh[2], hh[2], hl[2], ll[2];
#pragma unroll
        for (int k = 0; k < 2; ++k) {
            lh[k] = make_float2(0.f, 0.f); hh[k] = lh[k];
            hl[k] = lh[k]; ll[k] = lh[k];
        }
#pragma unroll
        for (int j = 0; j < 8; ++j) {
            float2 aj = *(const float2*)&slo[(rb + j) * SL1 + 2 * qx];
            float2 bj = *(const float2*)&shi[(rb + j) * SL1 + 2 * qx];
#pragma unroll
            for (int k = 0; k < 2; ++k) {
                const int t1 = j - k;
                if (t1 >= 0 && t1 < 7) {
                    float2 h = dup2(c_h1o[6 - t1]);
                    lh[k] = ffma2(h, aj, lh[k]);
                    hh[k] = ffma2(h, bj, hh[k]);
                }
                const int t0 = j - 1 - k;
                if (t0 >= 0 && t0 < 5) {
                    float2 h = dup2(c_h0o[4 - t0]);
                    hl[k] = ffma2(h, bj, hl[k]);
                    ll[k] = ffma2(h, aj, ll[k]);
                }
            }
        }
#pragma unroll
        for (int k = 0; k < 2; ++k)
            *(float2*)&g_ll1[((size_t)plane * 512 + ty0 + rb + k) * 512 + tx0 + 2 * qx] = ll[k];
        const int gqy = (ty0 >> 1) + qr;
        float A, B, C, D;
        A = lh[0].x; B = lh[0].y; C = lh[1].x; D = lh[1].y;
        __stcs(&yo[((pb + 0) * 256 + gqy) * 256 + gqx], make_float2((A - D) * SQH, (B + C) * SQH));
        __stcs(&yo[((pb + 5) * 256 + gqy) * 256 + gqx], make_float2((A + D) * SQH, (B - C) * SQH));
        A = hh[0].x; B = hh[0].y; C = hh[1].x; D = hh[1].y;
        __stcs(&yo[((pb + 1) * 256 + gqy) * 256 + gqx], make_float2((A - D) * SQH, (B + C) * SQH));
        __stcs(&yo[((pb + 4) * 256 + gqy) * 256 + gqx], make_float2((A + D) * SQH, (B - C) * SQH));
        A = hl[0].x; B = hl[0].y; C = hl[1].x; D = hl[1].y;
        __stcs(&yo[((pb + 2) * 256 + gqy) * 256 + gqx], make_float2((A - D) * SQH, (B + C) * SQH));
        __stcs(&yo[((pb + 3) * 256 + gqy) * 256 + gqx], make_float2((A + D) * SQH, (B - C) * SQH));
    }
}

// ---------------------------------------------------------------------------
// Levels 2/3 (q-shift dfilt): tile 32x32 half-res out, 256 threads, 4 blk/SM.
// W-phase reads GMEM directly (sx staging removed — it had zero reuse).
// Regs UNCAPPED beyond 4-block budget (62) so xr[32] stays in registers.
// ---------------------------------------------------------------------------
constexpr int SLD = 68;  // slohi row stride (words) = 34 float2

template <int R, int LVL>
__global__ __launch_bounds__(256, 4) void k_dfilt(float* __restrict__ llout_arg,
                                                  float* __restrict__ yh) {
    constexpr int RH = R / 2, RQ = R / 4;
    __shared__ float slohi[80 * SLD];
    const int plane = blockIdx.z;
    const int u0 = blockIdx.x * 32, v0 = blockIdx.y * 32;
    const int tid = threadIdx.x;
    const float* inp = ((LVL == 2) ? g_ll1 : g_ll2) + (size_t)plane * R * R;
    float* llout = (LVL == 2) ? (g_ll2 + (size_t)plane * RH * RH)
                              : (llout_arg + (size_t)plane * RH * RH);
    const int rawr0 = 2 * v0 - 8, rawc0 = 2 * u0 - 8;

    // ---- W-phase dfilt straight from GMEM: 80 rows x 4 chunks of 8 cols ----
    for (int idx = tid; idx < 320; idx += 256) {
        const int r = idx % 80, chunk = idx / 80;
        const float* rowp = inp + (size_t)refl(rawr0 + r, R) * R;
        const int s = rawc0 + 16 * chunk;
        float xr[32];
        if (s >= 0 && s + 32 <= R) {
            const float4* v = (const float4*)(rowp + s);
#pragma unroll
            for (int q = 0; q < 8; ++q) ((float4*)xr)[q] = v[q];
        } else {
#pragma unroll
            for (int j = 0; j < 32; ++j) xr[j] = rowp[refl(s + j, R)];
        }
        float* srow = &slohi[r * SLD + chunk * 16];
#pragma unroll
        for (int k2 = 0; k2 < 4; ++k2) {
            const int r4 = 4 * k2;
            float loe = 0.f, hie = 0.f, loo = 0.f, hio = 0.f;
#pragma unroll
            for (int j = 0; j < 5; ++j) {
                loe = fmaf(c_h0b[8 - 2 * j], xr[r4 + 2 + 4 * j], loe);
                loe = fmaf(c_h0b[9 - 2 * j], xr[r4 + 4 * j], loe);
                hie = fmaf(c_h1a[8 - 2 * j], xr[r4 + 3 + 4 * j], hie);
                hie = fmaf(c_h1a[9 - 2 * j], xr[r4 + 1 + 4 * j], hie);
                loo = fmaf(c_h0a[8 - 2 * j], xr[r4 + 3 + 4 * j], loo);
                loo = fmaf(c_h0a[9 - 2 * j], xr[r4 + 1 + 4 * j], loo);
                hio = fmaf(c_h1b[8 - 2 * j], xr[r4 + 2 + 4 * j], hio);
                hio = fmaf(c_h1b[9 - 2 * j], xr[r4 + 4 * j], hio);
            }
            *(float4*)&srow[4 * k2] = make_float4(loe, hie, loo, hio);
        }
    }
    __syncthreads();

    // ---- H-phase dfilt + q2c: one thread per q-point (16x16) ----
    const int qx = tid & 15, qy = tid >> 4;
    float2 accL[2][2], accH[2][2];  // {ll,hl}[parity][col], {lh,hh}[parity][col]
#pragma unroll
    for (int p = 0; p < 2; ++p)
#pragma unroll
        for (int c = 0; c < 2; ++c) {
            accL[p][c] = make_float2(0.f, 0.f);
            accH[p][c] = make_float2(0.f, 0.f);
        }
    const float* wbase = &slohi[(4 * qy) * SLD + 4 * qx];
#pragma unroll
    for (int t = 0; t < 20; ++t) {
        float4 d = *(const float4*)&wbase[t * SLD];
        float2 dA = make_float2(d.x, d.y);  // col u0: {lo, hi}
        float2 dB = make_float2(d.z, d.w);  // col u0+1
        const int j = t >> 2, tm = t & 3;
        float cl, ch;
        int pl, ph;
        if (tm == 0)      { cl = c_h0b[9 - 2 * j]; ch = c_h1b[9 - 2 * j]; pl = 0; ph = 1; }
        else if (tm == 1) { cl = c_h0a[9 - 2 * j]; ch = c_h1a[9 - 2 * j]; pl = 1; ph = 0; }
        else if (tm == 2) { cl = c_h0b[8 - 2 * j]; ch = c_h1b[8 - 2 * j]; pl = 0; ph = 1; }
        else              { cl = c_h0a[8 - 2 * j]; ch = c_h1a[8 - 2 * j]; pl = 1; ph = 0; }
        float2 cld = dup2(cl), chd = dup2(ch);
        accL[pl][0] = ffma2(cld, dA, accL[pl][0]);
        accL[pl][1] = ffma2(cld, dB, accL[pl][1]);
        accH[ph][0] = ffma2(chd, dA, accH[ph][0]);
        accH[ph][1] = ffma2(chd, dB, accH[ph][1]);
    }

    // ll stores (half-res rows v0+2qy+p)
#pragma unroll
    for (int p = 0; p < 2; ++p) {
        float2 v = make_float2(accL[p][0].x, accL[p][1].x);
        float2* dst = (float2*)&llout[(size_t)(v0 + 2 * qy + p) * RH + u0 + 2 * qx];
        if (LVL == 3) __stcs(dst, v); else *dst = v;
    }

    // q2c
    float2* yo = (float2*)yh;
    const size_t pbq = (size_t)plane * 6;
    const int gqy = (v0 >> 1) + qy, gqx = (u0 >> 1) + qx;
    float A, B, C, D;
    A = accH[0][0].x; B = accH[0][1].x; C = accH[1][0].x; D = accH[1][1].x;  // lh
    __stcs(&yo[((pbq + 0) * RQ + gqy) * RQ + gqx], make_float2((A - D) * SQH, (B + C) * SQH));
    __stcs(&yo[((pbq + 5) * RQ + gqy) * RQ + gqx], make_float2((A + D) * SQH, (B - C) * SQH));
    A = accH[0][0].y; B = accH[0][1].y; C = accH[1][0].y; D = accH[1][1].y;  // hh
    __stcs(&yo[((pbq + 1) * RQ + gqy) * RQ + gqx], make_float2((A - D) * SQH, (B + C) * SQH));
    __stcs(&yo[((pbq + 4) * RQ + gqy) * RQ + gqx], make_float2((A + D) * SQH, (B - C) * SQH));
    A = accL[0][0].y; B = accL[0][1].y; C = accL[1][0].y; D = accL[1][1].y;  // hl
    __stcs(&yo[((pbq + 2) * RQ + gqy) * RQ + gqx], make_float2((A - D) * SQH, (B + C) * SQH));
    __stcs(&yo[((pbq + 3) * RQ + gqy) * RQ + gqx], make_float2((A + D) * SQH, (B - C) * SQH));
}

// ---------------------------------------------------------------------------
// launch
// ---------------------------------------------------------------------------
extern "C" void kernel_launch(void* const* d_in, const int* in_sizes, int n_in,
                              void* d_out, int out_size) {
    const float* x = (const float*)d_in[0];
    float* out = (float*)d_out;

    cudaFuncSetAttribute(k_level1, cudaFuncAttributeMaxDynamicSharedMemorySize, L1_SMEM);

    cudaMemcpyToSymbolAsync(c_h0o, d_in[1], 5 * sizeof(float), 0, cudaMemcpyDeviceToDevice, 0);
    cudaMemcpyToSymbolAsync(c_h1o, d_in[2], 7 * sizeof(float), 0, cudaMemcpyDeviceToDevice, 0);
    cudaMemcpyToSymbolAsync(c_h0a, d_in[3], 10 * sizeof(float), 0, cudaMemcpyDeviceToDevice, 0);
    cudaMemcpyToSymbolAsync(c_h0b, d_in[4], 10 * sizeof(float), 0, cudaMemcpyDeviceToDevice, 0);
    cudaMemcpyToSymbolAsync(c_h1a, d_in[5], 10 * sizeof(float), 0, cudaMemcpyDeviceToDevice, 0);
    cudaMemcpyToSymbolAsync(c_h1b, d_in[6], 10 * sizeof(float), 0, cudaMemcpyDeviceToDevice, 0);

    // float offsets into d_out: ll3 | yh0 | yh1 | yh2
    const size_t OUT_YH0 = 1048576;    // 64*128*128
    const size_t OUT_YH1 = 51380224;   // + 64*6*256*256*2
    const size_t OUT_YH2 = 63963136;   // + 64*6*128*128*2

    k_level1<<<dim3(8, 8, 64), 512, L1_SMEM>>>(x, out + OUT_YH0);
    k_dfilt<512, 2><<<dim3(8, 8, 64), 256>>>((float*)nullptr, out + OUT_YH1);
    k_dfilt<256, 3><<<dim3(4, 4, 64), 256>>>(out, out + OUT_YH2);
}

// round 13
// speedup vs baseline: 1.1343x; 1.1343x over previous
#include <cuda_runtime.h>

#define SQH 0.70710678118654752440f

__constant__ float c_h0o[5], c_h1o[7], c_h0a[10], c_h0b[10], c_h1a[10], c_h1b[10];

// scratch lowpass pyramids (64 planes)
__device__ float g_ll1[64u * 512u * 512u];  // 64 MB
__device__ float g_ll2[64u * 256u * 256u];  // 16 MB

__device__ __forceinline__ int refl(int p, int r) {
    if (p < 0) p = -1 - p;
    if (p >= r) p = 2 * r - 1 - p;
    return p;
}

// packed fp32x2 FMA (Blackwell): d = a*b + c per lane
__device__ __forceinline__ float2 ffma2(float2 a, float2 b, float2 c) {
    float2 d;
    asm("fma.rn.f32x2 %0, %1, %2, %3;"
        : "=l"(reinterpret_cast<unsigned long long&>(d))
        : "l"(reinterpret_cast<unsigned long long&>(a)),
          "l"(reinterpret_cast<unsigned long long&>(b)),
          "l"(reinterpret_cast<unsigned long long&>(c)));
    return d;
}
__device__ __forceinline__ float2 dup2(float v) { return make_float2(v, v); }

// ---------------------------------------------------------------------------
// Level 1: tile 64(h) x 64(w), 512 threads, 3 blocks/SM.
// sx: 70 rows x 72 cols (left halo 4 for aligned float4 loads), stride 76.
// slohi: interleaved {lo,hi} per col, 70 rows x 128 floats, stride 132.
// smem = (70*76 + 70*132)*4 = 58240 B.
// ---------------------------------------------------------------------------
constexpr int SX1 = 76;
constexpr int SLI = 132;
constexpr int L1_SMEM = (70 * SX1 + 70 * SLI) * 4;

__global__ __launch_bounds__(512, 3) void k_level1(const float* __restrict__ x,
                                                   float* __restrict__ yh0) {
    extern __shared__ float smem[];
    float* sx = smem;                  // 70 * 76 (cols = global tx0-4 .. tx0+67)
    float* slohi = smem + 70 * SX1;    // 70 * 132
    const int plane = blockIdx.z;
    const int tx0 = blockIdx.x * 64, ty0 = blockIdx.y * 64;
    const int tid = threadIdx.x;
    const float* xp = x + (size_t)plane * 262144;

    // ---- load x tile: rows ty0-3..+66 (70), cols tx0-4..+67 (72) ----
    if (ty0 >= 3 && ty0 + 67 <= 512 && tx0 >= 4 && tx0 + 68 <= 512) {
        // vectorized: 70 rows x 18 float4 = 1260
        const float4* p0 = (const float4*)(xp + (ty0 - 3) * 512 + (tx0 - 4));
#pragma unroll
        for (int k = 0; k < 3; ++k) {
            int idx = tid + k * 512;
            if (idx < 1260) {
                int rr = idx / 18, cc = idx - rr * 18;
                *(float4*)&sx[rr * SX1 + 4 * cc] = p0[rr * 128 + cc];
            }
        }
    } else {
        for (int idx = tid; idx < 5040; idx += 512) {
            int rr = idx / 72, cc = idx - rr * 72;
            sx[rr * SX1 + cc] = xp[(size_t)refl(ty0 - 3 + rr, 512) * 512 + refl(tx0 - 4 + cc, 512)];
        }
    }
    __syncthreads();

    // ---- row filter: 70 rows x 8 chunks of 8 cols = 560 units ----
    // window xr[0..15] = local cols [8c, 8c+15]; output col k: lo taps xr[k+2+j],
    // hi taps xr[k+1+j] (left halo is 4).
    for (int idx = tid; idx < 560; idx += 512) {
        int r = idx % 70, chunk = idx / 70;
        const float* rp = &sx[r * SX1 + chunk * 8];
        float xr[16];
        ((float4*)xr)[0] = *(const float4*)rp;
        ((float4*)xr)[1] = *(const float4*)(rp + 4);
        ((float4*)xr)[2] = *(const float4*)(rp + 8);
        ((float4*)xr)[3] = *(const float4*)(rp + 12);
        float lo[8], hi[8];
#pragma unroll
        for (int k = 0; k < 8; ++k) {
            float l = 0.f, h = 0.f;
#pragma unroll
            for (int j = 0; j < 5; ++j) l = fmaf(c_h0o[4 - j], xr[k + 2 + j], l);
#pragma unroll
            for (int j = 0; j < 7; ++j) h = fmaf(c_h1o[6 - j], xr[k + 1 + j], h);
            lo[k] = l; hi[k] = h;
        }
        float* srow = &slohi[r * SLI + chunk * 16];
#pragma unroll
        for (int k2 = 0; k2 < 4; ++k2)
            *(float4*)(srow + 4 * k2) =
                make_float4(lo[2 * k2], hi[2 * k2], lo[2 * k2 + 1], hi[2 * k2 + 1]);
    }
    __syncthreads();

    // ---- col filters + ll + q2c: 2 q-row units per thread ----
    const int qx = tid & 31;
    const int qr0 = tid >> 5;  // 0..15
    float2* yo = (float2*)yh0;
    const size_t pb = (size_t)plane * 6;
    const int gqx = (tx0 >> 1) + qx;
#pragma unroll
    for (int half = 0; half < 2; ++half) {
        const int qr = qr0 + 16 * half;
        const int rb = 2 * qr;
        float2 lh[2], hh[2], hl[2], ll[2];
#pragma unroll
        for (int k = 0; k < 2; ++k) {
            lh[k] = make_float2(0.f, 0.f); hh[k] = lh[k];
            hl[k] = lh[k]; ll[k] = lh[k];
        }
#pragma unroll
        for (int j = 0; j < 8; ++j) {
            float4 d = *(const float4*)&slohi[(rb + j) * SLI + 4 * qx];
            float2 aj = make_float2(d.x, d.z);  // lo: cols 2qx, 2qx+1
            float2 bj = make_float2(d.y, d.w);  // hi
#pragma unroll
            for (int k = 0; k < 2; ++k) {
                const int t1 = j - k;
                if (t1 >= 0 && t1 < 7) {
                    float2 h = dup2(c_h1o[6 - t1]);
                    lh[k] = ffma2(h, aj, lh[k]);
                    hh[k] = ffma2(h, bj, hh[k]);
                }
                const int t0 = j - 1 - k;
                if (t0 >= 0 && t0 < 5) {
                    float2 h = dup2(c_h0o[4 - t0]);
                    hl[k] = ffma2(h, bj, hl[k]);
                    ll[k] = ffma2(h, aj, ll[k]);
                }
            }
        }
#pragma unroll
        for (int k = 0; k < 2; ++k)
            *(float2*)&g_ll1[((size_t)plane * 512 + ty0 + rb + k) * 512 + tx0 + 2 * qx] = ll[k];
        const int gqy = (ty0 >> 1) + qr;
        float A, B, C, D;
        A = lh[0].x; B = lh[0].y; C = lh[1].x; D = lh[1].y;
        __stcs(&yo[((pb + 0) * 256 + gqy) * 256 + gqx], make_float2((A - D) * SQH, (B + C) * SQH));
        __stcs(&yo[((pb + 5) * 256 + gqy) * 256 + gqx], make_float2((A + D) * SQH, (B - C) * SQH));
        A = hh[0].x; B = hh[0].y; C = hh[1].x; D = hh[1].y;
        __stcs(&yo[((pb + 1) * 256 + gqy) * 256 + gqx], make_float2((A - D) * SQH, (B + C) * SQH));
        __stcs(&yo[((pb + 4) * 256 + gqy) * 256 + gqx], make_float2((A + D) * SQH, (B - C) * SQH));
        A = hl[0].x; B = hl[0].y; C = hl[1].x; D = hl[1].y;
        __stcs(&yo[((pb + 2) * 256 + gqy) * 256 + gqx], make_float2((A - D) * SQH, (B + C) * SQH));
        __stcs(&yo[((pb + 3) * 256 + gqy) * 256 + gqx], make_float2((A + D) * SQH, (B - C) * SQH));
    }
}

// ---------------------------------------------------------------------------
// Levels 2/3 (q-shift dfilt): staged R10 form (known good). 32x32 out tile,
// 256 threads, 4 blocks/SM.
// ---------------------------------------------------------------------------
constexpr int SXD = 84;  // sx row stride (words)
constexpr int SLD = 68;  // slohi row stride (words) = 34 float2

template <int R, int LVL>
__global__ __launch_bounds__(256, 4) void k_dfilt(float* __restrict__ llout_arg,
                                                  float* __restrict__ yh) {
    constexpr int RH = R / 2, RQ = R / 4;
    __shared__ float sx[80 * SXD];
    __shared__ float slohi[80 * SLD];
    const int plane = blockIdx.z;
    const int u0 = blockIdx.x * 32, v0 = blockIdx.y * 32;
    const int tid = threadIdx.x;
    const float* inp = ((LVL == 2) ? g_ll1 : g_ll2) + (size_t)plane * R * R;
    float* llout = (LVL == 2) ? (g_ll2 + (size_t)plane * RH * RH)
                              : (llout_arg + (size_t)plane * RH * RH);
    const int rawr0 = 2 * v0 - 8, rawc0 = 2 * u0 - 8;

    // ---- load 80x80 full-res tile (coalesced) ----
    if (rawr0 >= 0 && rawr0 + 80 <= R && rawc0 >= 0 && rawc0 + 80 <= R) {
        const float* p0 = inp + (size_t)rawr0 * R + rawc0;
#pragma unroll
        for (int k = 0; k < 25; ++k) {
            int idx = tid + k * 256;
            int rr = idx / 80, cc = idx - rr * 80;
            sx[rr * SXD + cc] = p0[(size_t)rr * R + cc];
        }
    } else {
        for (int idx = tid; idx < 6400; idx += 256) {
            int rr = idx / 80, cc = idx - rr * 80;
            sx[rr * SXD + cc] = inp[(size_t)refl(rawr0 + rr, R) * R + refl(rawc0 + cc, R)];
        }
    }
    __syncthreads();

    // ---- W-phase dfilt: 80 rows x 4 chunks of 8 half-res cols ----
    for (int idx = tid; idx < 320; idx += 256) {
        int r = idx % 80, chunk = idx / 80;
        const float* rp = &sx[r * SXD + chunk * 16];
        float xr[32];
#pragma unroll
        for (int q = 0; q < 8; ++q) ((float4*)xr)[q] = *(const float4*)(rp + 4 * q);
        float* srow = &slohi[r * SLD + chunk * 16];
#pragma unroll
        for (int k2 = 0; k2 < 4; ++k2) {
            const int r4 = 4 * k2;
            float loe = 0.f, hie = 0.f, loo = 0.f, hio = 0.f;
#pragma unroll
            for (int j = 0; j < 5; ++j) {
                loe = fmaf(c_h0b[8 - 2 * j], xr[r4 + 2 + 4 * j], loe);
                loe = fmaf(c_h0b[9 - 2 * j], xr[r4 + 4 * j], loe);
                hie = fmaf(c_h1a[8 - 2 * j], xr[r4 + 3 + 4 * j], hie);
                hie = fmaf(c_h1a[9 - 2 * j], xr[r4 + 1 + 4 * j], hie);
                loo = fmaf(c_h0a[8 - 2 * j], xr[r4 + 3 + 4 * j], loo);
                loo = fmaf(c_h0a[9 - 2 * j], xr[r4 + 1 + 4 * j], loo);
                hio = fmaf(c_h1b[8 - 2 * j], xr[r4 + 2 + 4 * j], hio);
                hio = fmaf(c_h1b[9 - 2 * j], xr[r4 + 4 * j], hio);
            }
            *(float4*)&srow[4 * k2] = make_float4(loe, hie, loo, hio);
        }
    }
    __syncthreads();

    // ---- H-phase dfilt + q2c: one thread per q-point (16x16) ----
    const int qx = tid & 15, qy = tid >> 4;
    float2 accL[2][2], accH[2][2];  // {ll,hl}[parity][col], {lh,hh}[parity][col]
#pragma unroll
    for (int p = 0; p < 2; ++p)
#pragma unroll
        for (int c = 0; c < 2; ++c) {
            accL[p][c] = make_float2(0.f, 0.f);
            accH[p][c] = make_float2(0.f, 0.f);
        }
    const float* wbase = &slohi[(4 * qy) * SLD + 4 * qx];
#pragma unroll
    for (int t = 0; t < 20; ++t) {
        float4 d = *(const float4*)&wbase[t * SLD];
        float2 dA = make_float2(d.x, d.y);  // col u0: {lo, hi}
        float2 dB = make_float2(d.z, d.w);  // col u0+1
        const int j = t >> 2, tm = t & 3;
        float cl, ch;
        int pl, ph;
        if (tm == 0)      { cl = c_h0b[9 - 2 * j]; ch = c_h1b[9 - 2 * j]; pl = 0; ph = 1; }
        else if (tm == 1) { cl = c_h0a[9 - 2 * j]; ch = c_h1a[9 - 2 * j]; pl = 1; ph = 0; }
        else if (tm == 2) { cl = c_h0b[8 - 2 * j]; ch = c_h1b[8 - 2 * j]; pl = 0; ph = 1; }
        else              { cl = c_h0a[8 - 2 * j]; ch = c_h1a[8 - 2 * j]; pl = 1; ph = 0; }
        float2 cld = dup2(cl), chd = dup2(ch);
        accL[pl][0] = ffma2(cld, dA, accL[pl][0]);
        accL[pl][1] = ffma2(cld, dB, accL[pl][1]);
        accH[ph][0] = ffma2(chd, dA, accH[ph][0]);
        accH[ph][1] = ffma2(chd, dB, accH[ph][1]);
    }

    // ll stores (half-res rows v0+2qy+p)
#pragma unroll
    for (int p = 0; p < 2; ++p) {
        float2 v = make_float2(accL[p][0].x, accL[p][1].x);
        float2* dst = (float2*)&llout[(size_t)(v0 + 2 * qy + p) * RH + u0 + 2 * qx];
        if (LVL == 3) __stcs(dst, v); else *dst = v;
    }

    // q2c
    float2* yo = (float2*)yh;
    const size_t pbq = (size_t)plane * 6;
    const int gqy = (v0 >> 1) + qy, gqx = (u0 >> 1) + qx;
    float A, B, C, D;
    A = accH[0][0].x; B = accH[0][1].x; C = accH[1][0].x; D = accH[1][1].x;  // lh
    __stcs(&yo[((pbq + 0) * RQ + gqy) * RQ + gqx], make_float2((A - D) * SQH, (B + C) * SQH));
    __stcs(&yo[((pbq + 5) * RQ + gqy) * RQ + gqx], make_float2((A + D) * SQH, (B - C) * SQH));
    A = accH[0][0].y; B = accH[0][1].y; C = accH[1][0].y; D = accH[1][1].y;  // hh
    __stcs(&yo[((pbq + 1) * RQ + gqy) * RQ + gqx], make_float2((A - D) * SQH, (B + C) * SQH));
    __stcs(&yo[((pbq + 4) * RQ + gqy) * RQ + gqx], make_float2((A + D) * SQH, (B - C) * SQH));
    A = accL[0][0].y; B = accL[0][1].y; C = accL[1][0].y; D = accL[1][1].y;  // hl
    __stcs(&yo[((pbq + 2) * RQ + gqy) * RQ + gqx], make_float2((A - D) * SQH, (B + C) * SQH));
    __stcs(&yo[((pbq + 3) * RQ + gqy) * RQ + gqx], make_float2((A + D) * SQH, (B - C) * SQH));
}

// ---------------------------------------------------------------------------
// launch
// ---------------------------------------------------------------------------
extern "C" void kernel_launch(void* const* d_in, const int* in_sizes, int n_in,
                              void* d_out, int out_size) {
    const float* x = (const float*)d_in[0];
    float* out = (float*)d_out;

    cudaFuncSetAttribute(k_level1, cudaFuncAttributeMaxDynamicSharedMemorySize, L1_SMEM);

    cudaMemcpyToSymbolAsync(c_h0o, d_in[1], 5 * sizeof(float), 0, cudaMemcpyDeviceToDevice, 0);
    cudaMemcpyToSymbolAsync(c_h1o, d_in[2], 7 * sizeof(float), 0, cudaMemcpyDeviceToDevice, 0);
    cudaMemcpyToSymbolAsync(c_h0a, d_in[3], 10 * sizeof(float), 0, cudaMemcpyDeviceToDevice, 0);
    cudaMemcpyToSymbolAsync(c_h0b, d_in[4], 10 * sizeof(float), 0, cudaMemcpyDeviceToDevice, 0);
    cudaMemcpyToSymbolAsync(c_h1a, d_in[5], 10 * sizeof(float), 0, cudaMemcpyDeviceToDevice, 0);
    cudaMemcpyToSymbolAsync(c_h1b, d_in[6], 10 * sizeof(float), 0, cudaMemcpyDeviceToDevice, 0);

    // float offsets into d_out: ll3 | yh0 | yh1 | yh2
    const size_t OUT_YH0 = 1048576;    // 64*128*128
    const size_t OUT_YH1 = 51380224;   // + 64*6*256*256*2
    const size_t OUT_YH2 = 63963136;   // + 64*6*128*128*2

    k_level1<<<dim3(8, 8, 64), 512, L1_SMEM>>>(x, out + OUT_YH0);
    k_dfilt<512, 2><<<dim3(8, 8, 64), 256>>>((float*)nullptr, out + OUT_YH1);
    k_dfilt<256, 3><<<dim3(4, 4, 64), 256>>>(out, out + OUT_YH2);
}

// round 14
// speedup vs baseline: 1.1949x; 1.0534x over previous
#include <cuda_runtime.h>

#define SQH 0.70710678118654752440f

__constant__ float c_h0o[5], c_h1o[7], c_h0a[10], c_h0b[10], c_h1a[10], c_h1b[10];

// scratch lowpass pyramids (64 planes)
__device__ float g_ll1[64u * 512u * 512u];  // 64 MB
__device__ float g_ll2[64u * 256u * 256u];  // 16 MB

__device__ __forceinline__ int refl(int p, int r) {
    if (p < 0) p = -1 - p;
    if (p >= r) p = 2 * r - 1 - p;
    return p;
}

// packed fp32x2 FMA (Blackwell): d = a*b + c per lane
__device__ __forceinline__ float2 ffma2(float2 a, float2 b, float2 c) {
    float2 d;
    asm("fma.rn.f32x2 %0, %1, %2, %3;"
        : "=l"(reinterpret_cast<unsigned long long&>(d))
        : "l"(reinterpret_cast<unsigned long long&>(a)),
          "l"(reinterpret_cast<unsigned long long&>(b)),
          "l"(reinterpret_cast<unsigned long long&>(c)));
    return d;
}
__device__ __forceinline__ float2 dup2(float v) { return make_float2(v, v); }

// ---------------------------------------------------------------------------
// Level 1: tile 64(h) x 64(w), 512 threads, 3 blocks/SM.
// sx: 70 rows x 72 cols (left halo 4 -> aligned float4 loads), stride 76.
// slo/shi separate (aligned-pair LDS.64 for f32x2), stride 68.
// smem = (70*76 + 2*70*68)*4 = 59360 B.
// ---------------------------------------------------------------------------
constexpr int SX1 = 76;
constexpr int SL1 = 68;
constexpr int L1_SMEM = (70 * SX1 + 2 * 70 * SL1) * 4;

__global__ __launch_bounds__(512, 3) void k_level1(const float* __restrict__ x,
                                                   float* __restrict__ yh0) {
    extern __shared__ float smem[];
    float* sx = smem;                  // 70 * 76 (cols = global tx0-4 .. tx0+67)
    float* slo = smem + 70 * SX1;      // 70 * 68
    float* shi = slo + 70 * SL1;       // 70 * 68
    const int plane = blockIdx.z;
    const int tx0 = blockIdx.x * 64, ty0 = blockIdx.y * 64;
    const int tid = threadIdx.x;
    const float* xp = x + (size_t)plane * 262144;

    // ---- load x tile: rows ty0-3..+66 (70), cols tx0-4..+67 (72 = 18 float4) ----
    if (ty0 >= 3 && ty0 + 67 <= 512 && tx0 >= 4 && tx0 + 68 <= 512) {
        const float4* p0 = (const float4*)(xp + (ty0 - 3) * 512 + (tx0 - 4));
#pragma unroll
        for (int k = 0; k < 3; ++k) {
            int idx = tid + k * 512;
            if (idx < 1260) {
                int rr = idx / 18, cc = idx - rr * 18;
                *(float4*)&sx[rr * SX1 + 4 * cc] = p0[rr * 128 + cc];
            }
        }
    } else {
        for (int idx = tid; idx < 5040; idx += 512) {
            int rr = idx / 72, cc = idx - rr * 72;
            sx[rr * SX1 + cc] = xp[(size_t)refl(ty0 - 3 + rr, 512) * 512 + refl(tx0 - 4 + cc, 512)];
        }
    }
    __syncthreads();

    // ---- row filter: 70 rows x 8 chunks of 8 cols = 560 units ----
    // left halo 4: out col k -> lo taps xr[k+2+j], hi taps xr[k+1+j]
    for (int idx = tid; idx < 560; idx += 512) {
        int r = idx % 70, chunk = idx / 70;
        const float* rp = &sx[r * SX1 + chunk * 8];
        float xr[16];
        ((float4*)xr)[0] = *(const float4*)rp;
        ((float4*)xr)[1] = *(const float4*)(rp + 4);
        ((float4*)xr)[2] = *(const float4*)(rp + 8);
        ((float4*)xr)[3] = *(const float4*)(rp + 12);
        float lo[8], hi[8];
#pragma unroll
        for (int k = 0; k < 8; ++k) {
            float l = 0.f, h = 0.f;
#pragma unroll
            for (int j = 0; j < 5; ++j) l = fmaf(c_h0o[4 - j], xr[k + 2 + j], l);
#pragma unroll
            for (int j = 0; j < 7; ++j) h = fmaf(c_h1o[6 - j], xr[k + 1 + j], h);
            lo[k] = l; hi[k] = h;
        }
        float* sl = &slo[r * SL1 + chunk * 8];
        float* sh = &shi[r * SL1 + chunk * 8];
        *(float4*)sl = make_float4(lo[0], lo[1], lo[2], lo[3]);
        *(float4*)(sl + 4) = make_float4(lo[4], lo[5], lo[6], lo[7]);
        *(float4*)sh = make_float4(hi[0], hi[1], hi[2], hi[3]);
        *(float4*)(sh + 4) = make_float4(hi[4], hi[5], hi[6], hi[7]);
    }
    __syncthreads();

    // ---- col filters + ll + q2c: 2 q-row units per thread (R10 form) ----
    const int qx = tid & 31;
    const int qr0 = tid >> 5;  // 0..15
    float2* yo = (float2*)yh0;
    const size_t pb = (size_t)plane * 6;
    const int gqx = (tx0 >> 1) + qx;
#pragma unroll
    for (int half = 0; half < 2; ++half) {
        const int qr = qr0 + 16 * half;
        const int rb = 2 * qr;
        float2 lh[2], hh[2], hl[2], ll[2];
#pragma unroll
        for (int k = 0; k < 2; ++k) {
            lh[k] = make_float2(0.f, 0.f); hh[k] = lh[k];
            hl[k] = lh[k]; ll[k] = lh[k];
        }
#pragma unroll
        for (int j = 0; j < 8; ++j) {
            float2 aj = *(const float2*)&slo[(rb + j) * SL1 + 2 * qx];
            float2 bj = *(const float2*)&shi[(rb + j) * SL1 + 2 * qx];
#pragma unroll
            for (int k = 0; k < 2; ++k) {
                const int t1 = j - k;
                if (t1 >= 0 && t1 < 7) {
                    float2 h = dup2(c_h1o[6 - t1]);
                    lh[k] = ffma2(h, aj, lh[k]);
                    hh[k] = ffma2(h, bj, hh[k]);
                }
                const int t0 = j - 1 - k;
                if (t0 >= 0 && t0 < 5) {
                    float2 h = dup2(c_h0o[4 - t0]);
                    hl[k] = ffma2(h, bj, hl[k]);
                    ll[k] = ffma2(h, aj, ll[k]);
                }
            }
        }
#pragma unroll
        for (int k = 0; k < 2; ++k)
            *(float2*)&g_ll1[((size_t)plane * 512 + ty0 + rb + k) * 512 + tx0 + 2 * qx] = ll[k];
        const int gqy = (ty0 >> 1) + qr;
        float A, B, C, D;
        A = lh[0].x; B = lh[0].y; C = lh[1].x; D = lh[1].y;
        __stcs(&yo[((pb + 0) * 256 + gqy) * 256 + gqx], make_float2((A - D) * SQH, (B + C) * SQH));
        __stcs(&yo[((pb + 5) * 256 + gqy) * 256 + gqx], make_float2((A + D) * SQH, (B - C) * SQH));
        A = hh[0].x; B = hh[0].y; C = hh[1].x; D = hh[1].y;
        __stcs(&yo[((pb + 1) * 256 + gqy) * 256 + gqx], make_float2((A - D) * SQH, (B + C) * SQH));
        __stcs(&yo[((pb + 4) * 256 + gqy) * 256 + gqx], make_float2((A + D) * SQH, (B - C) * SQH));
        A = hl[0].x; B = hl[0].y; C = hl[1].x; D = hl[1].y;
        __stcs(&yo[((pb + 2) * 256 + gqy) * 256 + gqx], make_float2((A - D) * SQH, (B + C) * SQH));
        __stcs(&yo[((pb + 3) * 256 + gqy) * 256 + gqx], make_float2((A + D) * SQH, (B - C) * SQH));
    }
}

// ---------------------------------------------------------------------------
// Levels 2/3 (q-shift dfilt): staged, 32x32 out tile, 256 threads, 4 blk/SM.
// Interior tile load vectorized: 1600 LDG.128/STS.128 instead of 6400 scalar.
// ---------------------------------------------------------------------------
constexpr int SXD = 84;  // sx row stride (words)
constexpr int SLD = 68;  // slohi row stride (words) = 34 float2

template <int R, int LVL>
__global__ __launch_bounds__(256, 4) void k_dfilt(float* __restrict__ llout_arg,
                                                  float* __restrict__ yh) {
    constexpr int RH = R / 2, RQ = R / 4;
    __shared__ float sx[80 * SXD];
    __shared__ float slohi[80 * SLD];
    const int plane = blockIdx.z;
    const int u0 = blockIdx.x * 32, v0 = blockIdx.y * 32;
    const int tid = threadIdx.x;
    const float* inp = ((LVL == 2) ? g_ll1 : g_ll2) + (size_t)plane * R * R;
    float* llout = (LVL == 2) ? (g_ll2 + (size_t)plane * RH * RH)
                              : (llout_arg + (size_t)plane * RH * RH);
    const int rawr0 = 2 * v0 - 8, rawc0 = 2 * u0 - 8;

    // ---- load 80x80 full-res tile ----
    if (rawr0 >= 0 && rawr0 + 80 <= R && rawc0 >= 0 && rawc0 + 80 <= R) {
        // interior: vectorized (rawc0 = 64*bx - 8, mult of 4) -> 80 rows x 20 float4
        const float4* p0 = (const float4*)(inp + (size_t)rawr0 * R + rawc0);
#pragma unroll
        for (int k = 0; k < 7; ++k) {
            int idx = tid + k * 256;
            if (idx < 1600) {
                int rr = idx / 20, cc = idx - rr * 20;
                *(float4*)&sx[rr * SXD + 4 * cc] = p0[rr * (R / 4) + cc];
            }
        }
    } else {
        for (int idx = tid; idx < 6400; idx += 256) {
            int rr = idx / 80, cc = idx - rr * 80;
            sx[rr * SXD + cc] = inp[(size_t)refl(rawr0 + rr, R) * R + refl(rawc0 + cc, R)];
        }
    }
    __syncthreads();

    // ---- W-phase dfilt: 80 rows x 4 chunks of 8 half-res cols ----
    for (int idx = tid; idx < 320; idx += 256) {
        int r = idx % 80, chunk = idx / 80;
        const float* rp = &sx[r * SXD + chunk * 16];
        float xr[32];
#pragma unroll
        for (int q = 0; q < 8; ++q) ((float4*)xr)[q] = *(const float4*)(rp + 4 * q);
        float* srow = &slohi[r * SLD + chunk * 16];
#pragma unroll
        for (int k2 = 0; k2 < 4; ++k2) {
            const int r4 = 4 * k2;
            float loe = 0.f, hie = 0.f, loo = 0.f, hio = 0.f;
#pragma unroll
            for (int j = 0; j < 5; ++j) {
                loe = fmaf(c_h0b[8 - 2 * j], xr[r4 + 2 + 4 * j], loe);
                loe = fmaf(c_h0b[9 - 2 * j], xr[r4 + 4 * j], loe);
                hie = fmaf(c_h1a[8 - 2 * j], xr[r4 + 3 + 4 * j], hie);
                hie = fmaf(c_h1a[9 - 2 * j], xr[r4 + 1 + 4 * j], hie);
                loo = fmaf(c_h0a[8 - 2 * j], xr[r4 + 3 + 4 * j], loo);
                loo = fmaf(c_h0a[9 - 2 * j], xr[r4 + 1 + 4 * j], loo);
                hio = fmaf(c_h1b[8 - 2 * j], xr[r4 + 2 + 4 * j], hio);
                hio = fmaf(c_h1b[9 - 2 * j], xr[r4 + 4 * j], hio);
            }
            *(float4*)&srow[4 * k2] = make_float4(loe, hie, loo, hio);
        }
    }
    __syncthreads();

    // ---- H-phase dfilt + q2c: one thread per q-point (16x16) ----
    const int qx = tid & 15, qy = tid >> 4;
    float2 accL[2][2], accH[2][2];  // {ll,hl}[parity][col], {lh,hh}[parity][col]
#pragma unroll
    for (int p = 0; p < 2; ++p)
#pragma unroll
        for (int c = 0; c < 2; ++c) {
            accL[p][c] = make_float2(0.f, 0.f);
            accH[p][c] = make_float2(0.f, 0.f);
        }
    const float* wbase = &slohi[(4 * qy) * SLD + 4 * qx];
#pragma unroll
    for (int t = 0; t < 20; ++t) {
        float4 d = *(const float4*)&wbase[t * SLD];
        float2 dA = make_float2(d.x, d.y);  // col u0: {lo, hi}
        float2 dB = make_float2(d.z, d.w);  // col u0+1
        const int j = t >> 2, tm = t & 3;
        float cl, ch;
        int pl, ph;
        if (tm == 0)      { cl = c_h0b[9 - 2 * j]; ch = c_h1b[9 - 2 * j]; pl = 0; ph = 1; }
        else if (tm == 1) { cl = c_h0a[9 - 2 * j]; ch = c_h1a[9 - 2 * j]; pl = 1; ph = 0; }
        else if (tm == 2) { cl = c_h0b[8 - 2 * j]; ch = c_h1b[8 - 2 * j]; pl = 0; ph = 1; }
        else              { cl = c_h0a[8 - 2 * j]; ch = c_h1a[8 - 2 * j]; pl = 1; ph = 0; }
        float2 cld = dup2(cl), chd = dup2(ch);
        accL[pl][0] = ffma2(cld, dA, accL[pl][0]);
        accL[pl][1] = ffma2(cld, dB, accL[pl][1]);
        accH[ph][0] = ffma2(chd, dA, accH[ph][0]);
        accH[ph][1] = ffma2(chd, dB, accH[ph][1]);
    }

    // ll stores (half-res rows v0+2qy+p)
#pragma unroll
    for (int p = 0; p < 2; ++p) {
        float2 v = make_float2(accL[p][0].x, accL[p][1].x);
        float2* dst = (float2*)&llout[(size_t)(v0 + 2 * qy + p) * RH + u0 + 2 * qx];
        if (LVL == 3) __stcs(dst, v); else *dst = v;
    }

    // q2c
    float2* yo = (float2*)yh;
    const size_t pbq = (size_t)plane * 6;
    const int gqy = (v0 >> 1) + qy, gqx = (u0 >> 1) + qx;
    float A, B, C, D;
    A = accH[0][0].x; B = accH[0][1].x; C = accH[1][0].x; D = accH[1][1].x;  // lh
    __stcs(&yo[((pbq + 0) * RQ + gqy) * RQ + gqx], make_float2((A - D) * SQH, (B + C) * SQH));
    __stcs(&yo[((pbq + 5) * RQ + gqy) * RQ + gqx], make_float2((A + D) * SQH, (B - C) * SQH));
    A = accH[0][0].y; B = accH[0][1].y; C = accH[1][0].y; D = accH[1][1].y;  // hh
    __stcs(&yo[((pbq + 1) * RQ + gqy) * RQ + gqx], make_float2((A - D) * SQH, (B + C) * SQH));
    __stcs(&yo[((pbq + 4) * RQ + gqy) * RQ + gqx], make_float2((A + D) * SQH, (B - C) * SQH));
    A = accL[0][0].y; B = accL[0][1].y; C = accL[1][0].y; D = accL[1][1].y;  // hl
    __stcs(&yo[((pbq + 2) * RQ + gqy) * RQ + gqx], make_float2((A - D) * SQH, (B + C) * SQH));
    __stcs(&yo[((pbq + 3) * RQ + gqy) * RQ + gqx], make_float2((A + D) * SQH, (B - C) * SQH));
}

// ---------------------------------------------------------------------------
// launch
// ---------------------------------------------------------------------------
extern "C" void kernel_launch(void* const* d_in, const int* in_sizes, int n_in,
                              void* d_out, int out_size) {
    const float* x = (const float*)d_in[0];
    float* out = (float*)d_out;

    cudaFuncSetAttribute(k_level1, cudaFuncAttributeMaxDynamicSharedMemorySize, L1_SMEM);

    cudaMemcpyToSymbolAsync(c_h0o, d_in[1], 5 * sizeof(float), 0, cudaMemcpyDeviceToDevice, 0);
    cudaMemcpyToSymbolAsync(c_h1o, d_in[2], 7 * sizeof(float), 0, cudaMemcpyDeviceToDevice, 0);
    cudaMemcpyToSymbolAsync(c_h0a, d_in[3], 10 * sizeof(float), 0, cudaMemcpyDeviceToDevice, 0);
    cudaMemcpyToSymbolAsync(c_h0b, d_in[4], 10 * sizeof(float), 0, cudaMemcpyDeviceToDevice, 0);
    cudaMemcpyToSymbolAsync(c_h1a, d_in[5], 10 * sizeof(float), 0, cudaMemcpyDeviceToDevice, 0);
    cudaMemcpyToSymbolAsync(c_h1b, d_in[6], 10 * sizeof(float), 0, cudaMemcpyDeviceToDevice, 0);

    // float offsets into d_out: ll3 | yh0 | yh1 | yh2
    const size_t OUT_YH0 = 1048576;    // 64*128*128
    const size_t OUT_YH1 = 51380224;   // + 64*6*256*256*2
    const size_t OUT_YH2 = 63963136;   // + 64*6*128*128*2

    k_level1<<<dim3(8, 8, 64), 512, L1_SMEM>>>(x, out + OUT_YH0);
    k_dfilt<512, 2><<<dim3(8, 8, 64), 256>>>((float*)nullptr, out + OUT_YH1);
    k_dfilt<256, 3><<<dim3(4, 4, 64), 256>>>(out, out + OUT_YH2);
}